// round 4
// baseline (speedup 1.0000x reference)
#include <cuda_runtime.h>
#include <math.h>

#define BB   8
#define NA   4096
#define NAA  1024
#define NPC  4096
#define KNB  16
#define KNC  14
#define GG   32
#define DA   12
#define FF   128
#define DD   128
#define NATTR 39     // NCAT+1
#define APB  16      // atoms per block in atom_kernel
#define RPAD 20      // padded row length for Mt/yt (bank spread, 16B aligned)

// -------- scratch (static device globals; no allocation allowed) ----------
__device__ float g_att   [BB*NA*DD];    // 16 MB
__device__ float g_feat  [BB*NA*DD];    // 16 MB
__device__ float g_masky [BB*NA];       // 128 KB
__device__ float g_pooled[BB*NAA*DD];   // 4 MB
__device__ float g_mean  [DD];
__device__ float g_invstd[DD];

// -------- packed f32x2 helpers (SASS FFMA2 path) --------------------------
__device__ __forceinline__ unsigned long long pk2(float lo, float hi) {
    unsigned long long r;
    asm("mov.b64 %0, {%1, %2};" : "=l"(r) : "f"(lo), "f"(hi));
    return r;
}
__device__ __forceinline__ void fma2(unsigned long long& d,
                                     unsigned long long a,
                                     unsigned long long b) {
    asm("fma.rn.f32x2 %0, %1, %2, %0;" : "+l"(d) : "l"(a), "l"(b));
}
__device__ __forceinline__ float2 upk2(unsigned long long v) {
    float2 f;
    asm("mov.b64 {%0, %1}, %2;" : "=f"(f.x), "=f"(f.y) : "l"(v));
    return f;
}

// dynamic shared layout for atom_kernel (~90 KB -> 2 blocks/SM)
struct __align__(16) SmemA {
    float Mt  [GG*DA][RPAD];     // M transposed: [r][atom], atoms contiguous
    float yt  [FF][RPAD];        // y transposed: [f][atom]
    float g   [APB][KNB][33];    // padded inner dim (bank spread)
    float anb [APB][KNB][DA];
    float attr[NATTR*DA];
    float mattr[NATTR];
    float gc  [GG*3];
    float R   [APB][9];
    float c   [APB][3];
    float masky[APB];
};

// ==========================================================================
// Kernel A: per-atom. 16 atoms per block, 256 threads.
// ==========================================================================
__global__ __launch_bounds__(256) void atom_kernel(
    const float* __restrict__ pc,         // (B,NPC,3)
    const float* __restrict__ mask_atom,  // (B,NA,1)
    const float* __restrict__ attr_table, // (39,12)
    const float* __restrict__ gauss,      // (32,3)
    const float* __restrict__ W_nem,      // (384,128)
    const float* __restrict__ W_att,      // (128,128)
    const float* __restrict__ W_feat,     // (128,128)
    const int*   __restrict__ frame_idx,  // (B,NA,3)
    const int*   __restrict__ attr_idx,   // (B,NA)
    const int*   __restrict__ nb_idx)     // (B,NA,16)
{
    extern __shared__ char smem_raw[];
    SmemA& S = *reinterpret_cast<SmemA*>(smem_raw);

    const int t  = threadIdx.x;
    const int ai = t >> 4;                 // 0..15 atom-in-block
    const int k  = t & 15;                 // neighbor
    const long gaBase = (long)blockIdx.x * APB;
    const long ga = gaBase + ai;
    const int  b  = (int)(ga >> 12);       // NA = 4096

    // ---- stage 0: small tables ----
    for (int i = t; i < NATTR*DA; i += 256) S.attr[i] = attr_table[i];
    for (int i = t; i < GG*3;     i += 256) S.gc[i]   = gauss[i];
    __syncthreads();

    // ---- stage 1: mattr rows + frames ----
    if (t < NATTR) {
        float any = 0.f;
        #pragma unroll
        for (int a = 0; a < DA; a++) if (S.attr[t*DA + a] != 0.f) any = 1.f;
        S.mattr[t] = any;
    }
    if (k == 0) {
        const int* fi = frame_idx + ga*3;
        const float* pb = pc + (long)b*NPC*3;
        int i0 = fi[0], i1 = fi[1], i2 = fi[2];
        float c0 = pb[i1*3+0], c1 = pb[i1*3+1], c2 = pb[i1*3+2];
        float a0 = pb[i2*3+0]-c0, a1 = pb[i2*3+1]-c1, a2 = pb[i2*3+2]-c2;
        float n1 = sqrtf(a0*a0 + a1*a1 + a2*a2);
        float s1 = 1.f / (n1 + 1e-8f);
        float u10 = a0*s1, u11 = a1*s1, u12 = a2*s1;
        float v0 = pb[i0*3+0]-c0, v1 = pb[i0*3+1]-c1, v2 = pb[i0*3+2]-c2;
        float dp = v0*u10 + v1*u11 + v2*u12;
        float w0 = v0 - dp*u10, w1 = v1 - dp*u11, w2 = v2 - dp*u12;
        float n2 = sqrtf(w0*w0 + w1*w1 + w2*w2);
        float s2 = 1.f / (n2 + 1e-8f);
        float u20 = w0*s2, u21 = w1*s2, u22 = w2*s2;
        float u30 = u11*u22 - u12*u21;
        float u31 = u12*u20 - u10*u22;
        float u32 = u10*u21 - u11*u20;
        S.R[ai][0]=u10; S.R[ai][1]=u11; S.R[ai][2]=u12;
        S.R[ai][3]=u20; S.R[ai][4]=u21; S.R[ai][5]=u22;
        S.R[ai][6]=u30; S.R[ai][7]=u31; S.R[ai][8]=u32;
        S.c[ai][0]=c0;  S.c[ai][1]=c1;  S.c[ai][2]=c2;
    }
    __syncthreads();

    // ---- stage 2: gaussians + neighbor attrs ----
    if (k == 0) {
        int own = attr_idx[ga];
        S.masky[ai] = mask_atom[ga] * S.mattr[own];
    }
    {
        int nb  = nb_idx[ga*KNB + k];
        long nbg = (long)b*NA + nb;
        int fi1 = frame_idx[nbg*3 + 1];
        const float* pb = pc + (long)b*NPC*3;
        float dx = pb[fi1*3+0] - S.c[ai][0];
        float dy = pb[fi1*3+1] - S.c[ai][1];
        float dz = pb[fi1*3+2] - S.c[ai][2];
        float r0 = S.R[ai][0]*dx + S.R[ai][1]*dy + S.R[ai][2]*dz;
        float r1 = S.R[ai][3]*dx + S.R[ai][4]*dy + S.R[ai][5]*dz;
        float r2 = S.R[ai][6]*dx + S.R[ai][7]*dy + S.R[ai][8]*dz;
        #pragma unroll
        for (int gi = 0; gi < GG; gi++) {
            float gx = r0 - S.gc[gi*3+0];
            float gy = r1 - S.gc[gi*3+1];
            float gz = r2 - S.gc[gi*3+2];
            S.g[ai][k][gi] = __expf(-0.5f * (gx*gx + gy*gy + gz*gz));
        }
        int na = attr_idx[nbg];
        float m = S.mattr[na];
        #pragma unroll
        for (int a = 0; a < DA; a++)
            S.anb[ai][k][a] = S.attr[na*DA + a] * m;
    }
    __syncthreads();

    // ---- stage 3: Mt[r][atom] = sum_k g*anb (transposed store) ----
    // quads: APB * GG * 3 = 1536 ; 6 per thread
    for (int q = t; q < APB*GG*(DA/4); q += 256) {
        int a2 = q / (GG*(DA/4));
        int r  = q - a2*(GG*(DA/4));
        int gi = r / (DA/4);
        int aq = r - gi*(DA/4);
        float4 acc = make_float4(0.f,0.f,0.f,0.f);
        const float4* anb4 = (const float4*)&S.anb[a2][0][0];  // [KNB][3]
        #pragma unroll
        for (int kk = 0; kk < KNB; kk++) {
            float gv = S.g[a2][kk][gi];
            float4 av = anb4[kk*(DA/4) + aq];
            acc.x += gv*av.x; acc.y += gv*av.y; acc.z += gv*av.z; acc.w += gv*av.w;
        }
        int rr = gi*DA + aq*4;
        S.Mt[rr+0][a2] = acc.x;
        S.Mt[rr+1][a2] = acc.y;
        S.Mt[rr+2][a2] = acc.z;
        S.Mt[rr+3][a2] = acc.w;
    }
    __syncthreads();

    // ---- stage 4: y[f] = (M . W_nem)/K * mask ----
    // thread: f = t&127, half = t>>7 handles atoms [half*8, half*8+8)
    {
        const int f    = t & 127;
        const int half = t >> 7;
        unsigned long long acc[4];
        #pragma unroll
        for (int j = 0; j < 4; j++) acc[j] = 0ull;
        const float* wp = W_nem + f;
        #pragma unroll 4
        for (int r = 0; r < GG*DA; r++) {
            float w = wp[r*FF];
            unsigned long long ws = pk2(w, w);
            const ulonglong2* mp = (const ulonglong2*)&S.Mt[r][half*8];
            ulonglong2 m01 = mp[0];
            ulonglong2 m23 = mp[1];
            fma2(acc[0], m01.x, ws);
            fma2(acc[1], m01.y, ws);
            fma2(acc[2], m23.x, ws);
            fma2(acc[3], m23.y, ws);
        }
        const float inv16 = 1.f/(float)KNB;
        #pragma unroll
        for (int j = 0; j < 4; j++) {
            float2 v = upk2(acc[j]);
            int a0 = half*8 + 2*j;
            S.yt[f][a0+0] = v.x * inv16 * S.masky[a0+0];
            S.yt[f][a0+1] = v.y * inv16 * S.masky[a0+1];
        }
    }
    __syncthreads();

    // ---- stage 5: att/feat = y @ W ----
    {
        const int d    = t & 127;
        const int half = t >> 7;
        unsigned long long aA2[4], aF2[4];
        #pragma unroll
        for (int j = 0; j < 4; j++) { aA2[j] = 0ull; aF2[j] = 0ull; }
        const float* wa_p = W_att  + d;
        const float* wf_p = W_feat + d;
        #pragma unroll 4
        for (int f = 0; f < FF; f++) {
            float wa = wa_p[f*DD];
            float wf = wf_p[f*DD];
            unsigned long long was = pk2(wa, wa);
            unsigned long long wfs = pk2(wf, wf);
            const ulonglong2* yp = (const ulonglong2*)&S.yt[f][half*8];
            ulonglong2 y01 = yp[0];
            ulonglong2 y23 = yp[1];
            fma2(aA2[0], y01.x, was);
            fma2(aA2[1], y01.y, was);
            fma2(aA2[2], y23.x, was);
            fma2(aA2[3], y23.y, was);
            fma2(aF2[0], y01.x, wfs);
            fma2(aF2[1], y01.y, wfs);
            fma2(aF2[2], y23.x, wfs);
            fma2(aF2[3], y23.y, wfs);
        }
        #pragma unroll
        for (int j = 0; j < 4; j++) {
            float2 va = upk2(aA2[j]);
            float2 vf = upk2(aF2[j]);
            int a0 = half*8 + 2*j;
            float m0 = S.masky[a0+0];
            float m1 = S.masky[a0+1];
            g_att [(gaBase+a0+0)*DD + d] = va.x * m0;
            g_att [(gaBase+a0+1)*DD + d] = va.y * m1;
            g_feat[(gaBase+a0+0)*DD + d] = vf.x * m0;
            g_feat[(gaBase+a0+1)*DD + d] = vf.y * m1;
        }
    }
    if (t < APB) g_masky[gaBase + t] = S.masky[t];
}

// ==========================================================================
// Kernel B: per-AA softmax pooling. 1 block per (b, aa), 128 threads = D.
// ==========================================================================
__global__ __launch_bounds__(128) void aa_kernel(
    const float* __restrict__ mask_aa,      // (B,NAA,1)
    const int*   __restrict__ seq_idx_atom, // (B,NA)
    const int*   __restrict__ seq_idx_aa,   // (B,NAA)
    const int*   __restrict__ aa_nb_idx)    // (B,NAA,14)
{
    const int t   = threadIdx.x;
    const long g2 = blockIdx.x;          // b*NAA + n
    const int b   = (int)(g2 >> 10);     // NAA = 1024

    __shared__ long  s_idx [KNC];
    __shared__ float s_gate[KNC];
    __shared__ float s_mnb [KNC];

    if (t < KNC) {
        int idx = aa_nb_idx[g2*KNC + t];
        long gi = (long)b*NA + idx;
        s_idx[t] = gi;
        int sn = seq_idx_atom[gi];
        int sa = seq_idx_aa[g2];
        s_gate[t] = (sn == sa) ? 1.f : 0.f;
        s_mnb[t]  = g_masky[gi];
    }
    __syncthreads();

    float l[KNC];
    float mx = -1e30f;
    #pragma unroll
    for (int j = 0; j < KNC; j++) {
        float v = (s_mnb[j] > 0.f) ? g_att[s_idx[j]*DD + t] : -1e9f;
        l[j] = v;
        mx = fmaxf(mx, v);
    }
    float E = 0.f;
    #pragma unroll
    for (int j = 0; j < KNC; j++) {
        l[j] = __expf(l[j] - mx);
        E += l[j];
    }
    float invE = 1.f / E;
    float wsum = 0.f;
    #pragma unroll
    for (int j = 0; j < KNC; j++) {
        float w = l[j] * invE * s_gate[j] * s_mnb[j];
        l[j] = w;
        wsum += w;
    }
    float p = 0.f;
    #pragma unroll
    for (int j = 0; j < KNC; j++)
        p += l[j] * g_feat[s_idx[j]*DD + t];
    p = p / (wsum + 1e-8f) * mask_aa[g2];
    g_pooled[g2*DD + t] = p;
}

// ==========================================================================
// Kernel C: per-channel masked mean/var over (B,NAA). 1 block per channel.
// ==========================================================================
__global__ __launch_bounds__(256) void stats_kernel(const float* __restrict__ mask_aa)
{
    const int d = blockIdx.x;
    const int t = threadIdx.x;
    float s1 = 0.f, s2 = 0.f, sm = 0.f;
    for (int r = t; r < BB*NAA; r += 256) {
        float m = mask_aa[r];
        float p = g_pooled[(long)r*DD + d];
        s1 += m*p; s2 += m*p*p; sm += m;
    }
    __shared__ float r1[256], r2[256], rm[256];
    r1[t] = s1; r2[t] = s2; rm[t] = sm;
    __syncthreads();
    for (int o = 128; o > 0; o >>= 1) {
        if (t < o) { r1[t] += r1[t+o]; r2[t] += r2[t+o]; rm[t] += rm[t+o]; }
        __syncthreads();
    }
    if (t == 0) {
        float n    = rm[0] + 1e-8f;
        float mean = r1[0] / n;
        float var  = (r2[0] - 2.f*mean*r1[0] + mean*mean*rm[0]) / n;
        g_mean[d]   = mean;
        g_invstd[d] = rsqrtf(var + 1e-5f);
    }
}

// ==========================================================================
// Kernel D: batchnorm affine + relu + write both outputs.
// ==========================================================================
__global__ __launch_bounds__(128) void final_kernel(
    const float* __restrict__ mask_aa,
    const float* __restrict__ bn_gamma,
    const float* __restrict__ bn_beta,
    float* __restrict__ out)
{
    const int t   = threadIdx.x;
    const long g2 = blockIdx.x;
    float m = mask_aa[g2];
    float p = g_pooled[g2*DD + t];
    float o = bn_gamma[t] * (p - g_mean[t]) * g_invstd[t] + bn_beta[t];
    o = fmaxf(o * m, 0.f);
    out[g2*DD + t] = o;
    if (t == 0) out[(long)BB*NAA*DD + g2] = m;   // second tuple element: mask_aa
}

// ==========================================================================
extern "C" void kernel_launch(void* const* d_in, const int* in_sizes, int n_in,
                              void* d_out, int out_size)
{
    const float* pc        = (const float*)d_in[0];
    const float* mask_atom = (const float*)d_in[1];
    const float* mask_aa   = (const float*)d_in[2];
    const float* attr      = (const float*)d_in[3];
    const float* gauss     = (const float*)d_in[4];
    const float* wnem      = (const float*)d_in[5];
    const float* watt      = (const float*)d_in[6];
    const float* wfeat     = (const float*)d_in[7];
    const float* gamma     = (const float*)d_in[8];
    const float* beta      = (const float*)d_in[9];
    const int*   fidx      = (const int*)d_in[10];
    const int*   aidx      = (const int*)d_in[11];
    const int*   nbidx     = (const int*)d_in[12];
    const int*   seqa      = (const int*)d_in[13];
    const int*   seqaa     = (const int*)d_in[14];
    const int*   aanb      = (const int*)d_in[15];
    float* out = (float*)d_out;

    cudaFuncSetAttribute(atom_kernel,
                         cudaFuncAttributeMaxDynamicSharedMemorySize,
                         (int)sizeof(SmemA));

    atom_kernel<<<BB*NA/APB, 256, sizeof(SmemA)>>>(pc, mask_atom, attr, gauss,
                                                   wnem, watt, wfeat,
                                                   fidx, aidx, nbidx);
    aa_kernel<<<BB*NAA, 128>>>(mask_aa, seqa, seqaa, aanb);
    stats_kernel<<<DD, 256>>>(mask_aa);
    final_kernel<<<BB*NAA, 128>>>(mask_aa, gamma, beta, out);
}

// round 5
// speedup vs baseline: 1.3220x; 1.3220x over previous
#include <cuda_runtime.h>
#include <math.h>

#define BB   8
#define NA   4096
#define NAA  1024
#define NPC  4096
#define KNB  16
#define KNC  14
#define GG   32
#define DA   12
#define FF   128
#define DD   128
#define NATTR 39     // NCAT+1
#define APB  8       // atoms per block in atom_kernel
#define GP   33      // padded inner dim of sh_g (bank spread)

// -------- scratch (static device globals; no allocation allowed) ----------
__device__ float g_att   [BB*NA*DD];    // 16 MB
__device__ float g_feat  [BB*NA*DD];    // 16 MB
__device__ float g_masky [BB*NA];       // 128 KB
__device__ float g_pooled[BB*NAA*DD];   // 4 MB
__device__ float g_mean  [DD];
__device__ float g_invstd[DD];

// -------- packed f32x2 helpers (SASS FFMA2 path) --------------------------
__device__ __forceinline__ unsigned long long pk2(float lo, float hi) {
    unsigned long long r;
    asm("mov.b64 %0, {%1, %2};" : "=l"(r) : "f"(lo), "f"(hi));
    return r;
}
__device__ __forceinline__ void fma2(unsigned long long& d,
                                     unsigned long long a,
                                     unsigned long long b) {
    asm("fma.rn.f32x2 %0, %1, %2, %0;" : "+l"(d) : "l"(a), "l"(b));
}
__device__ __forceinline__ float2 upk2(unsigned long long v) {
    float2 f;
    asm("mov.b64 {%0, %1}, %2;" : "=f"(f.x), "=f"(f.y) : "l"(v));
    return f;
}

// ==========================================================================
// Kernel A: per-atom. 8 atoms per block, 128 threads.
//   thread t = ai*16 + k  (ai = atom-in-block, k = neighbor)
// LDS.128 reads consumed directly as ulonglong2 (born-packed FFMA2 operands).
// ==========================================================================
__global__ __launch_bounds__(128) void atom_kernel(
    const float* __restrict__ pc,         // (B,NPC,3)
    const float* __restrict__ mask_atom,  // (B,NA,1)
    const float* __restrict__ attr_table, // (39,12)
    const float* __restrict__ gauss,      // (32,3)
    const float* __restrict__ W_nem,      // (384,128)
    const float* __restrict__ W_att,      // (128,128)
    const float* __restrict__ W_feat,     // (128,128)
    const int*   __restrict__ frame_idx,  // (B,NA,3)
    const int*   __restrict__ attr_idx,   // (B,NA)
    const int*   __restrict__ nb_idx)     // (B,NA,16)
{
    __shared__ float sh_attr [NATTR*DA];
    __shared__ float sh_mattr[NATTR];
    __shared__ float sh_gc   [GG*3];
    __shared__ float sh_R    [APB][9];
    __shared__ float sh_c    [APB][3];
    __shared__ float sh_masky[APB];
    __shared__ __align__(16) float sh_g   [APB][KNB][GP];
    __shared__ __align__(16) float sh_anb [APB][KNB][DA];
    __shared__ __align__(16) float sh_M   [APB][GG*DA];
    __shared__ __align__(16) float sh_y   [APB][FF];

    const int t  = threadIdx.x;
    const int ai = t >> 4;
    const int k  = t & 15;
    const long gaBase = (long)blockIdx.x * APB;
    const long ga = gaBase + ai;               // global atom id
    const int  b  = (int)(ga >> 12);           // NA = 4096

    // ---- stage 0: stage small tables in smem ----
    for (int i = t; i < NATTR*DA; i += 128) sh_attr[i] = attr_table[i];
    for (int i = t; i < GG*3;     i += 128) sh_gc[i]   = gauss[i];
    __syncthreads();

    // ---- stage 1: mattr per table row; frame R per atom ----
    if (t < NATTR) {
        float any = 0.f;
        #pragma unroll
        for (int a = 0; a < DA; a++) if (sh_attr[t*DA + a] != 0.f) any = 1.f;
        sh_mattr[t] = any;
    }
    if (k == 0) {
        const int* fi = frame_idx + ga*3;
        const float* pb = pc + (long)b*NPC*3;
        int i0 = fi[0], i1 = fi[1], i2 = fi[2];
        float c0 = pb[i1*3+0], c1 = pb[i1*3+1], c2 = pb[i1*3+2];
        float a0 = pb[i2*3+0]-c0, a1 = pb[i2*3+1]-c1, a2 = pb[i2*3+2]-c2;
        float n1 = sqrtf(a0*a0 + a1*a1 + a2*a2);
        float s1 = 1.f / (n1 + 1e-8f);
        float u10 = a0*s1, u11 = a1*s1, u12 = a2*s1;
        float v0 = pb[i0*3+0]-c0, v1 = pb[i0*3+1]-c1, v2 = pb[i0*3+2]-c2;
        float dp = v0*u10 + v1*u11 + v2*u12;
        float w0 = v0 - dp*u10, w1 = v1 - dp*u11, w2 = v2 - dp*u12;
        float n2 = sqrtf(w0*w0 + w1*w1 + w2*w2);
        float s2 = 1.f / (n2 + 1e-8f);
        float u20 = w0*s2, u21 = w1*s2, u22 = w2*s2;
        float u30 = u11*u22 - u12*u21;
        float u31 = u12*u20 - u10*u22;
        float u32 = u10*u21 - u11*u20;
        sh_R[ai][0]=u10; sh_R[ai][1]=u11; sh_R[ai][2]=u12;
        sh_R[ai][3]=u20; sh_R[ai][4]=u21; sh_R[ai][5]=u22;
        sh_R[ai][6]=u30; sh_R[ai][7]=u31; sh_R[ai][8]=u32;
        sh_c[ai][0]=c0;  sh_c[ai][1]=c1;  sh_c[ai][2]=c2;
    }
    __syncthreads();

    // ---- stage 2: per-(atom, neighbor): gaussian features + attr gather ----
    if (k == 0) {
        int own = attr_idx[ga];
        sh_masky[ai] = mask_atom[ga] * sh_mattr[own];
    }
    {
        int nb  = nb_idx[ga*KNB + k];             // [0, NA)
        long nbg = (long)b*NA + nb;
        int fi1 = frame_idx[nbg*3 + 1];
        const float* pb = pc + (long)b*NPC*3;
        float dx = pb[fi1*3+0] - sh_c[ai][0];
        float dy = pb[fi1*3+1] - sh_c[ai][1];
        float dz = pb[fi1*3+2] - sh_c[ai][2];
        float r0 = sh_R[ai][0]*dx + sh_R[ai][1]*dy + sh_R[ai][2]*dz;
        float r1 = sh_R[ai][3]*dx + sh_R[ai][4]*dy + sh_R[ai][5]*dz;
        float r2 = sh_R[ai][6]*dx + sh_R[ai][7]*dy + sh_R[ai][8]*dz;
        #pragma unroll
        for (int gi = 0; gi < GG; gi++) {
            float gx = r0 - sh_gc[gi*3+0];
            float gy = r1 - sh_gc[gi*3+1];
            float gz = r2 - sh_gc[gi*3+2];
            sh_g[ai][k][gi] = __expf(-0.5f * (gx*gx + gy*gy + gz*gz));
        }
        int na = attr_idx[nbg];
        float m = sh_mattr[na];
        #pragma unroll
        for (int a = 0; a < DA; a++)
            sh_anb[ai][k][a] = sh_attr[na*DA + a] * m;
    }
    __syncthreads();

    // ---- stage 3: M[ai][gi][a] = sum_k g * a_nb  (born-packed FFMA2) ----
    for (int q = t; q < APB*GG*(DA/4); q += 128) {
        int a2 = q / (GG*(DA/4));
        int r  = q - a2*(GG*(DA/4));
        int gi = r / (DA/4);
        int aq = r - gi*(DA/4);
        unsigned long long acc01 = 0ull, acc23 = 0ull;
        const ulonglong2* anb2 = (const ulonglong2*)&sh_anb[a2][0][0]; // [KNB][3]
        #pragma unroll
        for (int kk = 0; kk < KNB; kk++) {
            float gv = sh_g[a2][kk][gi];
            unsigned long long gg = pk2(gv, gv);
            ulonglong2 av = anb2[kk*(DA/4) + aq];
            fma2(acc01, av.x, gg);
            fma2(acc23, av.y, gg);
        }
        ulonglong2 res; res.x = acc01; res.y = acc23;
        ((ulonglong2*)&sh_M[a2][0])[gi*(DA/4) + aq] = res;
    }
    __syncthreads();

    // ---- stage 4: y[f] = (M . W_nem)/K * mask ----  thread t = f
    {
        unsigned long long acc2[APB];
        #pragma unroll
        for (int i = 0; i < APB; i++) acc2[i] = 0ull;
        const float* wp = W_nem + t;
        for (int r4 = 0; r4 < GG*DA/4; r4++) {
            float w0 = wp[(r4*4+0)*FF];
            float w1 = wp[(r4*4+1)*FF];
            float w2 = wp[(r4*4+2)*FF];
            float w3 = wp[(r4*4+3)*FF];
            unsigned long long w01 = pk2(w0, w1);
            unsigned long long w23 = pk2(w2, w3);
            #pragma unroll
            for (int i = 0; i < APB; i++) {
                ulonglong2 m2 = ((const ulonglong2*)&sh_M[i][0])[r4];
                fma2(acc2[i], m2.x, w01);
                fma2(acc2[i], m2.y, w23);
            }
        }
        #pragma unroll
        for (int i = 0; i < APB; i++) {
            float2 f = upk2(acc2[i]);
            sh_y[i][t] = (f.x + f.y) * (1.f/(float)KNB) * sh_masky[i];
        }
    }
    __syncthreads();

    // ---- stage 5: att/feat = y @ W ----  thread t = d, born-packed over f
    {
        unsigned long long aA2[APB], aF2[APB];
        #pragma unroll
        for (int i = 0; i < APB; i++) { aA2[i] = 0ull; aF2[i] = 0ull; }
        const float* wa_p = W_att  + t;
        const float* wf_p = W_feat + t;
        for (int f4 = 0; f4 < FF/4; f4++) {
            float wa0 = wa_p[(f4*4+0)*DD], wa1 = wa_p[(f4*4+1)*DD];
            float wa2 = wa_p[(f4*4+2)*DD], wa3 = wa_p[(f4*4+3)*DD];
            float wf0 = wf_p[(f4*4+0)*DD], wf1 = wf_p[(f4*4+1)*DD];
            float wf2 = wf_p[(f4*4+2)*DD], wf3 = wf_p[(f4*4+3)*DD];
            unsigned long long wa01 = pk2(wa0, wa1), wa23 = pk2(wa2, wa3);
            unsigned long long wf01 = pk2(wf0, wf1), wf23 = pk2(wf2, wf3);
            #pragma unroll
            for (int i = 0; i < APB; i++) {
                ulonglong2 y2 = ((const ulonglong2*)&sh_y[i][0])[f4];
                fma2(aA2[i], y2.x, wa01);
                fma2(aA2[i], y2.y, wa23);
                fma2(aF2[i], y2.x, wf01);
                fma2(aF2[i], y2.y, wf23);
            }
        }
        #pragma unroll
        for (int i = 0; i < APB; i++) {
            long gb = gaBase + i;
            float m = sh_masky[i];
            float2 fa = upk2(aA2[i]);
            float2 ff = upk2(aF2[i]);
            g_att [gb*DD + t] = (fa.x + fa.y) * m;
            g_feat[gb*DD + t] = (ff.x + ff.y) * m;
        }
    }
    if (t < APB) g_masky[gaBase + t] = sh_masky[t];
}

// ==========================================================================
// Kernel B: per-AA softmax pooling. 1 block per (b, aa), 128 threads = D.
// ==========================================================================
__global__ __launch_bounds__(128) void aa_kernel(
    const float* __restrict__ mask_aa,      // (B,NAA,1)
    const int*   __restrict__ seq_idx_atom, // (B,NA)
    const int*   __restrict__ seq_idx_aa,   // (B,NAA)
    const int*   __restrict__ aa_nb_idx)    // (B,NAA,14)
{
    const int t   = threadIdx.x;
    const long g2 = blockIdx.x;          // b*NAA + n
    const int b   = (int)(g2 >> 10);     // NAA = 1024

    __shared__ long  s_idx [KNC];
    __shared__ float s_gate[KNC];
    __shared__ float s_mnb [KNC];

    if (t < KNC) {
        int idx = aa_nb_idx[g2*KNC + t];
        long gi = (long)b*NA + idx;
        s_idx[t] = gi;
        int sn = seq_idx_atom[gi];
        int sa = seq_idx_aa[g2];
        s_gate[t] = (sn == sa) ? 1.f : 0.f;
        s_mnb[t]  = g_masky[gi];
    }
    __syncthreads();

    float l[KNC];
    float mx = -1e30f;
    #pragma unroll
    for (int j = 0; j < KNC; j++) {
        float v = (s_mnb[j] > 0.f) ? g_att[s_idx[j]*DD + t] : -1e9f;
        l[j] = v;
        mx = fmaxf(mx, v);
    }
    float E = 0.f;
    #pragma unroll
    for (int j = 0; j < KNC; j++) {
        l[j] = __expf(l[j] - mx);
        E += l[j];
    }
    float invE = 1.f / E;
    float wsum = 0.f;
    #pragma unroll
    for (int j = 0; j < KNC; j++) {
        float w = l[j] * invE * s_gate[j] * s_mnb[j];
        l[j] = w;
        wsum += w;
    }
    float p = 0.f;
    #pragma unroll
    for (int j = 0; j < KNC; j++)
        p += l[j] * g_feat[s_idx[j]*DD + t];
    p = p / (wsum + 1e-8f) * mask_aa[g2];
    g_pooled[g2*DD + t] = p;
}

// ==========================================================================
// Kernel C: per-channel masked mean/var over (B,NAA). 1 block per channel.
// ==========================================================================
__global__ __launch_bounds__(256) void stats_kernel(const float* __restrict__ mask_aa)
{
    const int d = blockIdx.x;
    const int t = threadIdx.x;
    float s1 = 0.f, s2 = 0.f, sm = 0.f;
    for (int r = t; r < BB*NAA; r += 256) {
        float m = mask_aa[r];
        float p = g_pooled[(long)r*DD + d];
        s1 += m*p; s2 += m*p*p; sm += m;
    }
    __shared__ float r1[256], r2[256], rm[256];
    r1[t] = s1; r2[t] = s2; rm[t] = sm;
    __syncthreads();
    for (int o = 128; o > 0; o >>= 1) {
        if (t < o) { r1[t] += r1[t+o]; r2[t] += r2[t+o]; rm[t] += rm[t+o]; }
        __syncthreads();
    }
    if (t == 0) {
        float n    = rm[0] + 1e-8f;
        float mean = r1[0] / n;
        float var  = (r2[0] - 2.f*mean*r1[0] + mean*mean*rm[0]) / n;
        g_mean[d]   = mean;
        g_invstd[d] = rsqrtf(var + 1e-5f);
    }
}

// ==========================================================================
// Kernel D: batchnorm affine + relu + write both outputs.
// ==========================================================================
__global__ __launch_bounds__(128) void final_kernel(
    const float* __restrict__ mask_aa,
    const float* __restrict__ bn_gamma,
    const float* __restrict__ bn_beta,
    float* __restrict__ out)
{
    const int t   = threadIdx.x;
    const long g2 = blockIdx.x;
    float m = mask_aa[g2];
    float p = g_pooled[g2*DD + t];
    float o = bn_gamma[t] * (p - g_mean[t]) * g_invstd[t] + bn_beta[t];
    o = fmaxf(o * m, 0.f);
    out[g2*DD + t] = o;
    if (t == 0) out[(long)BB*NAA*DD + g2] = m;   // second tuple element: mask_aa
}

// ==========================================================================
extern "C" void kernel_launch(void* const* d_in, const int* in_sizes, int n_in,
                              void* d_out, int out_size)
{
    const float* pc        = (const float*)d_in[0];
    const float* mask_atom = (const float*)d_in[1];
    const float* mask_aa   = (const float*)d_in[2];
    const float* attr      = (const float*)d_in[3];
    const float* gauss     = (const float*)d_in[4];
    const float* wnem      = (const float*)d_in[5];
    const float* watt      = (const float*)d_in[6];
    const float* wfeat     = (const float*)d_in[7];
    const float* gamma     = (const float*)d_in[8];
    const float* beta      = (const float*)d_in[9];
    const int*   fidx      = (const int*)d_in[10];
    const int*   aidx      = (const int*)d_in[11];
    const int*   nbidx     = (const int*)d_in[12];
    const int*   seqa      = (const int*)d_in[13];
    const int*   seqaa     = (const int*)d_in[14];
    const int*   aanb      = (const int*)d_in[15];
    float* out = (float*)d_out;

    atom_kernel<<<BB*NA/APB, 128>>>(pc, mask_atom, attr, gauss, wnem, watt, wfeat,
                                    fidx, aidx, nbidx);
    aa_kernel<<<BB*NAA, 128>>>(mask_aa, seqa, seqaa, aanb);
    stats_kernel<<<DD, 256>>>(mask_aa);
    final_kernel<<<BB*NAA, 128>>>(mask_aa, gamma, beta, out);
}